// round 2
// baseline (speedup 1.0000x reference)
#include <cuda_runtime.h>
#include <cstdint>

#define NN 512000       // nodes = 512 * 1000
#define NE 8192000      // edges per branch
#define NB 512          // batch
#define NS 1000         // stations
#define NH 64           // ff hidden
#define NA 1024         // actions
#define EPSF 1e-5f

// ---------------- scratch (static device globals; no runtime alloc) ----------
__device__ float    g_stats[3][16];        // per branch: sum[8], sumsq[8]
__device__ unsigned g_deg[3][NN];          // edge-count per dst (self loop added later)
__device__ float    g_A[3][32];            // fused norm*W1, [i*4+j]
__device__ float    g_dvec[3][4];          // fused norm bias through W1
__device__ float4   g_z1[3][NN];           // xw * dinv
__device__ float4   g_acc1[3][NN];         // conv1 accumulator (init = z1 = self loop)
__device__ float    g_z2[3][NN];
__device__ float    g_acc2[3][NN];
__device__ float    g_concat[NB][3 * NS];  // [512, 3000]
__device__ float    g_hidden[NB][NH];      // [512, 64]

// ---------------- kernels ----------------------------------------------------

__global__ void zeroK() {
    int i = blockIdx.x * blockDim.x + threadIdx.x;
    if (i < 3 * NN) ((unsigned*)g_deg)[i] = 0u;
    if (i < 48)     ((float*)g_stats)[i] = 0.f;
}

// per-feature sum and sum-of-squares over all nodes of one branch
__global__ void statsK(const float* __restrict__ x, int br) {
    float s[8], q[8];
#pragma unroll
    for (int i = 0; i < 8; i++) { s[i] = 0.f; q[i] = 0.f; }
    int stride = gridDim.x * blockDim.x;
    for (int n = blockIdx.x * blockDim.x + threadIdx.x; n < NN; n += stride) {
        const float4* p = (const float4*)(x + (size_t)n * 8);
        float4 a = __ldg(p), b = __ldg(p + 1);
        float v[8] = {a.x, a.y, a.z, a.w, b.x, b.y, b.z, b.w};
#pragma unroll
        for (int i = 0; i < 8; i++) { s[i] += v[i]; q[i] += v[i] * v[i]; }
    }
#pragma unroll
    for (int i = 0; i < 8; i++) {
#pragma unroll
        for (int o = 16; o; o >>= 1) {
            s[i] += __shfl_down_sync(0xffffffffu, s[i], o);
            q[i] += __shfl_down_sync(0xffffffffu, q[i], o);
        }
    }
    __shared__ float sh[16];
    if (threadIdx.x < 16) sh[threadIdx.x] = 0.f;
    __syncthreads();
    if ((threadIdx.x & 31) == 0) {
#pragma unroll
        for (int i = 0; i < 8; i++) {
            atomicAdd(&sh[i], s[i]);
            atomicAdd(&sh[8 + i], q[i]);
        }
    }
    __syncthreads();
    if (threadIdx.x < 16) atomicAdd(&g_stats[br][threadIdx.x], sh[threadIdx.x]);
}

// histogram of dst indices (deg excluding self loop)
__global__ void degK(const int* __restrict__ ei, int br) {
    int e = blockIdx.x * blockDim.x + threadIdx.x;
    if (e < NE) {
        int d = __ldg(ei + NE + e);
        atomicAdd(&g_deg[br][d], 1u);
    }
}

// fold GraphNorm affine into W1: A = diag(a)*W1, dvec = d @ W1
__global__ void coefK(const float* __restrict__ nw, const float* __restrict__ nb,
                      const float* __restrict__ nms, const float* __restrict__ W1) {
    int br = threadIdx.x;
    if (br >= 3) return;
    const float inv = 1.0f / (float)NN;
    float a[8], d[8];
#pragma unroll
    for (int i = 0; i < 8; i++) {
        float mean = g_stats[br][i] * inv;
        float m2   = g_stats[br][8 + i] * inv;
        float c    = mean * nms[i];
        float var  = m2 - 2.f * c * mean + c * c;
        float ai   = nw[i] * rsqrtf(var + EPSF);
        a[i] = ai;
        d[i] = nb[i] - c * ai;
    }
#pragma unroll
    for (int j = 0; j < 4; j++) {
        float dv = 0.f;
#pragma unroll
        for (int i = 0; i < 8; i++) {
            g_A[br][i * 4 + j] = a[i] * W1[i * 4 + j];
            dv += d[i] * W1[i * 4 + j];
        }
        g_dvec[br][j] = dv;
    }
}

// z1 = (x @ A + dvec) * dinv ; acc1 init = z1 (self-loop term)
__global__ void z1K(const float* __restrict__ x, int br) {
    int n = blockIdx.x * blockDim.x + threadIdx.x;
    if (n >= NN) return;
    const float4* p = (const float4*)(x + (size_t)n * 8);
    float4 a = __ldg(p), b = __ldg(p + 1);
    float v[8] = {a.x, a.y, a.z, a.w, b.x, b.y, b.z, b.w};
    float dinv = rsqrtf((float)(g_deg[br][n] + 1u));
    float o[4];
#pragma unroll
    for (int j = 0; j < 4; j++) {
        float acc = g_dvec[br][j];
#pragma unroll
        for (int i = 0; i < 8; i++) acc += v[i] * g_A[br][i * 4 + j];
        o[j] = acc * dinv;
    }
    float4 z = make_float4(o[0], o[1], o[2], o[3]);
    g_z1[br][n]  = z;
    g_acc1[br][n] = z;
}

// conv1 edge scatter: acc1[dst] += z1[src]  (one 128-bit RED per edge)
__global__ void scat1K(const int* __restrict__ ei, int br) {
    int e = blockIdx.x * blockDim.x + threadIdx.x;
    if (e >= NE) return;
    int s = __ldg(ei + e);
    int d = __ldg(ei + NE + e);
    float4 z = g_z1[br][s];
    atomicAdd(&g_acc1[br][d], z);   // sm_90+: vector float4 RED.128
}

// h1 = relu(dinv*acc1 + b1) (never stored); z2 = (h1 . w2) * dinv; acc2 init = z2
__global__ void h1z2K(const float* __restrict__ b1, const float* __restrict__ w2, int br) {
    int n = blockIdx.x * blockDim.x + threadIdx.x;
    if (n >= NN) return;
    float dinv = rsqrtf((float)(g_deg[br][n] + 1u));
    float4 acc = g_acc1[br][n];
    float h0 = fmaxf(fmaf(dinv, acc.x, b1[0]), 0.f);
    float h1 = fmaxf(fmaf(dinv, acc.y, b1[1]), 0.f);
    float h2 = fmaxf(fmaf(dinv, acc.z, b1[2]), 0.f);
    float h3 = fmaxf(fmaf(dinv, acc.w, b1[3]), 0.f);
    float z2 = (h0 * w2[0] + h1 * w2[1] + h2 * w2[2] + h3 * w2[3]) * dinv;
    g_z2[br][n]  = z2;
    g_acc2[br][n] = z2;
}

// conv2 edge scatter: acc2[dst] += z2[src]
__global__ void scat2K(const int* __restrict__ ei, int br) {
    int e = blockIdx.x * blockDim.x + threadIdx.x;
    if (e >= NE) return;
    int s = __ldg(ei + e);
    int d = __ldg(ei + NE + e);
    atomicAdd(&g_acc2[br][d], g_z2[br][s]);
}

// final per-node conv2 epilogue + reshape/concat into [512, 3000]
__global__ void outK(const float* __restrict__ b2, int br) {
    int n = blockIdx.x * blockDim.x + threadIdx.x;
    if (n >= NN) return;
    float dinv = rsqrtf((float)(g_deg[br][n] + 1u));
    float v = fmaxf(fmaf(dinv, g_acc2[br][n], b2[0]), 0.f);
    int b = n / NS;
    int s = n - b * NS;
    g_concat[b][br * NS + s] = v;
}

// [512,3000] @ [3000,64] + relu
__global__ void ff1K(const float* __restrict__ w, const float* __restrict__ bias) {
    __shared__ float row[3 * NS];
    __shared__ float part[4][NH];
    int b = blockIdx.x;
    for (int k = threadIdx.x; k < 3 * NS; k += blockDim.x) row[k] = g_concat[b][k];
    __syncthreads();
    int g = threadIdx.x >> 6;
    int j = threadIdx.x & 63;
    float acc = 0.f;
    int k0 = g * 750, k1 = k0 + 750;
    for (int k = k0; k < k1; ++k) acc += row[k] * __ldg(w + (size_t)k * NH + j);
    part[g][j] = acc;
    __syncthreads();
    if (threadIdx.x < NH) {
        float v = part[0][threadIdx.x] + part[1][threadIdx.x] +
                  part[2][threadIdx.x] + part[3][threadIdx.x] + bias[threadIdx.x];
        g_hidden[b][threadIdx.x] = fmaxf(v, 0.f);
    }
}

// [512,64] @ [64,1024] + bias, * mask
__global__ void ff2K(const float* __restrict__ w, const float* __restrict__ bias,
                     const float* __restrict__ mask, float* __restrict__ out) {
    __shared__ float h[NH];
    int b = blockIdx.x;
    if (threadIdx.x < NH) h[threadIdx.x] = g_hidden[b][threadIdx.x];
    __syncthreads();
    for (int o = threadIdx.x; o < NA; o += blockDim.x) {
        float acc = bias[o];
#pragma unroll 8
        for (int k = 0; k < NH; k++) acc += h[k] * __ldg(w + (size_t)k * NA + o);
        out[(size_t)b * NA + o] = acc * mask[(size_t)b * NA + o];
    }
}

// ---------------- launch ------------------------------------------------------

extern "C" void kernel_launch(void* const* d_in, const int* in_sizes, int n_in,
                              void* d_out, int out_size) {
    const float* x[3]  = {(const float*)d_in[0], (const float*)d_in[1], (const float*)d_in[2]};
    const int* ei[3]   = {(const int*)d_in[3], (const int*)d_in[4], (const int*)d_in[5]};
    const float* mask = (const float*)d_in[6];
    const float* nw  = (const float*)d_in[7];
    const float* nb  = (const float*)d_in[8];
    const float* nms = (const float*)d_in[9];
    const float* W1  = (const float*)d_in[10];
    const float* b1  = (const float*)d_in[11];
    const float* W2  = (const float*)d_in[12];
    const float* b2  = (const float*)d_in[13];
    const float* wf1 = (const float*)d_in[14];
    const float* bf1 = (const float*)d_in[15];
    const float* wf2 = (const float*)d_in[16];
    const float* bf2 = (const float*)d_in[17];
    float* out = (float*)d_out;

    const int TB = 256;
    const int GN = (NN + TB - 1) / TB;
    const int GE = (NE + TB - 1) / TB;

    zeroK<<<(3 * NN + TB - 1) / TB, TB>>>();
    for (int br = 0; br < 3; br++) statsK<<<1024, TB>>>(x[br], br);
    for (int br = 0; br < 3; br++) degK<<<GE, TB>>>(ei[br], br);
    coefK<<<1, 32>>>(nw, nb, nms, W1);
    for (int br = 0; br < 3; br++) z1K<<<GN, TB>>>(x[br], br);
    for (int br = 0; br < 3; br++) scat1K<<<GE, TB>>>(ei[br], br);
    for (int br = 0; br < 3; br++) h1z2K<<<GN, TB>>>(b1, W2, br);
    for (int br = 0; br < 3; br++) scat2K<<<GE, TB>>>(ei[br], br);
    for (int br = 0; br < 3; br++) outK<<<GN, TB>>>(b2, br);
    ff1K<<<NB, TB>>>(wf1, bf1);
    ff2K<<<NB, TB>>>(wf2, bf2, mask, out);
}

// round 3
// speedup vs baseline: 1.1017x; 1.1017x over previous
#include <cuda_runtime.h>
#include <cstdint>

#define NN 512000       // nodes = 512 * 1000
#define NE 8192000      // edges per branch
#define NB 512          // batch
#define NS 1000         // stations
#define NH 64           // ff hidden
#define NA 1024         // actions
#define EPSF 1e-5f

#define STATS_BLKS 1024
#define EDGE_BLKS  8000         // 8000 * 256 * 4 = NE exactly

// ---------------- scratch ----------------------------------------------------
__device__ float    g_stats[3][16];        // per branch: sum[8], sumsq[8]
__device__ unsigned g_deg[3][NN];          // edge-count per dst (no self loop)
__device__ float    g_A[3][32];            // fused norm*W1
__device__ float    g_dvec[3][4];          // fused norm bias through W1
__device__ float4   g_z1[3][NN];           // xw * dinv (read-only during scat1)
__device__ float4   g_acc1[3][NN];         // conv1 accumulator (init = self loop)
__device__ float    g_z2[3][NN];
__device__ float    g_acc2[3][NN];
__device__ float    g_hidden[NB][NH];      // [512, 64]

// ---------------- kernels ----------------------------------------------------

__global__ void zeroK() {
    int i = blockIdx.x * blockDim.x + threadIdx.x;
    if (i < 3 * NN) ((unsigned*)g_deg)[i] = 0u;
    if (i < 48)     ((float*)g_stats)[i] = 0.f;
}

// fused: blocks [0,STATS_BLKS) do feature stats (streaming), the rest do the
// deg histogram (random atomics). blockIdx.y selects the branch. The streaming
// work hides inside the wavefront-bound histogram time.
__global__ void statsdegK(const float* __restrict__ x0, const float* __restrict__ x1,
                          const float* __restrict__ x2,
                          const int* __restrict__ e0, const int* __restrict__ e1,
                          const int* __restrict__ e2) {
    int br = blockIdx.y;
    if (blockIdx.x < STATS_BLKS) {
        const float* x = br == 0 ? x0 : (br == 1 ? x1 : x2);
        float s[8], q[8];
#pragma unroll
        for (int i = 0; i < 8; i++) { s[i] = 0.f; q[i] = 0.f; }
        int stride = STATS_BLKS * blockDim.x;
        for (int n = blockIdx.x * blockDim.x + threadIdx.x; n < NN; n += stride) {
            const float4* p = (const float4*)(x + (size_t)n * 8);
            float4 a = __ldg(p), b = __ldg(p + 1);
            float v[8] = {a.x, a.y, a.z, a.w, b.x, b.y, b.z, b.w};
#pragma unroll
            for (int i = 0; i < 8; i++) { s[i] += v[i]; q[i] += v[i] * v[i]; }
        }
#pragma unroll
        for (int i = 0; i < 8; i++) {
#pragma unroll
            for (int o = 16; o; o >>= 1) {
                s[i] += __shfl_down_sync(0xffffffffu, s[i], o);
                q[i] += __shfl_down_sync(0xffffffffu, q[i], o);
            }
        }
        __shared__ float sh[16];
        if (threadIdx.x < 16) sh[threadIdx.x] = 0.f;
        __syncthreads();
        if ((threadIdx.x & 31) == 0) {
#pragma unroll
            for (int i = 0; i < 8; i++) {
                atomicAdd(&sh[i], s[i]);
                atomicAdd(&sh[8 + i], q[i]);
            }
        }
        __syncthreads();
        if (threadIdx.x < 16) atomicAdd(&g_stats[br][threadIdx.x], sh[threadIdx.x]);
    } else {
        const int* ei = br == 0 ? e0 : (br == 1 ? e1 : e2);
        int base = (blockIdx.x - STATS_BLKS) * 1024 + threadIdx.x * 4;
        int4 d4 = __ldg((const int4*)(ei + NE + base));
        atomicAdd(&g_deg[br][d4.x], 1u);
        atomicAdd(&g_deg[br][d4.y], 1u);
        atomicAdd(&g_deg[br][d4.z], 1u);
        atomicAdd(&g_deg[br][d4.w], 1u);
    }
}

// fold GraphNorm affine into W1
__global__ void coefK(const float* __restrict__ nw, const float* __restrict__ nb,
                      const float* __restrict__ nms, const float* __restrict__ W1) {
    int br = threadIdx.x;
    if (br >= 3) return;
    const float inv = 1.0f / (float)NN;
    float a[8], d[8];
#pragma unroll
    for (int i = 0; i < 8; i++) {
        float mean = g_stats[br][i] * inv;
        float m2   = g_stats[br][8 + i] * inv;
        float c    = mean * nms[i];
        float var  = m2 - 2.f * c * mean + c * c;
        float ai   = nw[i] * rsqrtf(var + EPSF);
        a[i] = ai;
        d[i] = nb[i] - c * ai;
    }
#pragma unroll
    for (int j = 0; j < 4; j++) {
        float dv = 0.f;
#pragma unroll
        for (int i = 0; i < 8; i++) {
            g_A[br][i * 4 + j] = a[i] * W1[i * 4 + j];
            dv += d[i] * W1[i * 4 + j];
        }
        g_dvec[br][j] = dv;
    }
}

// z1 = (x @ A + dvec) * dinv ; acc1 init = z1 (self-loop term)
__global__ void z1K(const float* __restrict__ x0, const float* __restrict__ x1,
                    const float* __restrict__ x2) {
    int br = blockIdx.y;
    const float* x = br == 0 ? x0 : (br == 1 ? x1 : x2);
    int n = blockIdx.x * blockDim.x + threadIdx.x;
    if (n >= NN) return;
    const float4* p = (const float4*)(x + (size_t)n * 8);
    float4 a = __ldg(p), b = __ldg(p + 1);
    float v[8] = {a.x, a.y, a.z, a.w, b.x, b.y, b.z, b.w};
    float dinv = rsqrtf((float)(g_deg[br][n] + 1u));
    float o[4];
#pragma unroll
    for (int j = 0; j < 4; j++) {
        float acc = g_dvec[br][j];
#pragma unroll
        for (int i = 0; i < 8; i++) acc += v[i] * g_A[br][i * 4 + j];
        o[j] = acc * dinv;
    }
    float4 z = make_float4(o[0], o[1], o[2], o[3]);
    g_z1[br][n]  = z;
    g_acc1[br][n] = z;
}

// conv1 edge scatter, 4 edges/thread: acc1[dst] += z1[src]
__global__ void scat1K(const int* __restrict__ e0, const int* __restrict__ e1,
                       const int* __restrict__ e2) {
    int br = blockIdx.y;
    const int* ei = br == 0 ? e0 : (br == 1 ? e1 : e2);
    int base = blockIdx.x * 1024 + threadIdx.x * 4;
    int4 s4 = __ldg((const int4*)(ei + base));
    int4 d4 = __ldg((const int4*)(ei + NE + base));
    float4 z0 = __ldg(&g_z1[br][s4.x]);
    float4 z1 = __ldg(&g_z1[br][s4.y]);
    float4 z2 = __ldg(&g_z1[br][s4.z]);
    float4 z3 = __ldg(&g_z1[br][s4.w]);
    atomicAdd(&g_acc1[br][d4.x], z0);
    atomicAdd(&g_acc1[br][d4.y], z1);
    atomicAdd(&g_acc1[br][d4.z], z2);
    atomicAdd(&g_acc1[br][d4.w], z3);
}

// h1 = relu(dinv*acc1 + b1); z2 = (h1 . w2) * dinv; acc2 init = z2
__global__ void h1z2K(const float* __restrict__ b1, const float* __restrict__ w2) {
    int br = blockIdx.y;
    int n = blockIdx.x * blockDim.x + threadIdx.x;
    if (n >= NN) return;
    float dinv = rsqrtf((float)(g_deg[br][n] + 1u));
    float4 acc = g_acc1[br][n];
    float h0 = fmaxf(fmaf(dinv, acc.x, b1[0]), 0.f);
    float h1 = fmaxf(fmaf(dinv, acc.y, b1[1]), 0.f);
    float h2 = fmaxf(fmaf(dinv, acc.z, b1[2]), 0.f);
    float h3 = fmaxf(fmaf(dinv, acc.w, b1[3]), 0.f);
    float z2 = (h0 * w2[0] + h1 * w2[1] + h2 * w2[2] + h3 * w2[3]) * dinv;
    g_z2[br][n]  = z2;
    g_acc2[br][n] = z2;
}

// conv2 edge scatter, 4 edges/thread: acc2[dst] += z2[src]
__global__ void scat2K(const int* __restrict__ e0, const int* __restrict__ e1,
                       const int* __restrict__ e2) {
    int br = blockIdx.y;
    const int* ei = br == 0 ? e0 : (br == 1 ? e1 : e2);
    int base = blockIdx.x * 1024 + threadIdx.x * 4;
    int4 s4 = __ldg((const int4*)(ei + base));
    int4 d4 = __ldg((const int4*)(ei + NE + base));
    float v0 = __ldg(&g_z2[br][s4.x]);
    float v1 = __ldg(&g_z2[br][s4.y]);
    float v2 = __ldg(&g_z2[br][s4.z]);
    float v3 = __ldg(&g_z2[br][s4.w]);
    atomicAdd(&g_acc2[br][d4.x], v0);
    atomicAdd(&g_acc2[br][d4.y], v1);
    atomicAdd(&g_acc2[br][d4.z], v2);
    atomicAdd(&g_acc2[br][d4.w], v3);
}

// fused conv2 epilogue + concat + ff1: per block b, build concat row then GEMV
__global__ void ff1K(const float* __restrict__ b2, const float* __restrict__ w,
                     const float* __restrict__ bias) {
    __shared__ float row[3 * NS];
    __shared__ float part[4][NH];
    int b = blockIdx.x;
    for (int k = threadIdx.x; k < 3 * NS; k += blockDim.x) {
        int br = k / NS;
        int s  = k - br * NS;
        int n  = b * NS + s;
        float dinv = rsqrtf((float)(g_deg[br][n] + 1u));
        row[k] = fmaxf(fmaf(dinv, g_acc2[br][n], b2[0]), 0.f);
    }
    __syncthreads();
    int g = threadIdx.x >> 6;
    int j = threadIdx.x & 63;
    float acc = 0.f;
    int k0 = g * 750, k1 = k0 + 750;
    for (int k = k0; k < k1; ++k) acc += row[k] * __ldg(w + (size_t)k * NH + j);
    part[g][j] = acc;
    __syncthreads();
    if (threadIdx.x < NH) {
        float v = part[0][threadIdx.x] + part[1][threadIdx.x] +
                  part[2][threadIdx.x] + part[3][threadIdx.x] + bias[threadIdx.x];
        g_hidden[b][threadIdx.x] = fmaxf(v, 0.f);
    }
}

// [512,64] @ [64,1024] + bias, * mask
__global__ void ff2K(const float* __restrict__ w, const float* __restrict__ bias,
                     const float* __restrict__ mask, float* __restrict__ out) {
    __shared__ float h[NH];
    int b = blockIdx.x;
    if (threadIdx.x < NH) h[threadIdx.x] = g_hidden[b][threadIdx.x];
    __syncthreads();
    for (int o = threadIdx.x; o < NA; o += blockDim.x) {
        float acc = bias[o];
#pragma unroll 8
        for (int k = 0; k < NH; k++) acc += h[k] * __ldg(w + (size_t)k * NA + o);
        out[(size_t)b * NA + o] = acc * mask[(size_t)b * NA + o];
    }
}

// ---------------- launch ------------------------------------------------------

extern "C" void kernel_launch(void* const* d_in, const int* in_sizes, int n_in,
                              void* d_out, int out_size) {
    const float* x0 = (const float*)d_in[0];
    const float* x1 = (const float*)d_in[1];
    const float* x2 = (const float*)d_in[2];
    const int* e0 = (const int*)d_in[3];
    const int* e1 = (const int*)d_in[4];
    const int* e2 = (const int*)d_in[5];
    const float* mask = (const float*)d_in[6];
    const float* nw  = (const float*)d_in[7];
    const float* nb  = (const float*)d_in[8];
    const float* nms = (const float*)d_in[9];
    const float* W1  = (const float*)d_in[10];
    const float* b1  = (const float*)d_in[11];
    const float* W2  = (const float*)d_in[12];
    const float* b2  = (const float*)d_in[13];
    const float* wf1 = (const float*)d_in[14];
    const float* bf1 = (const float*)d_in[15];
    const float* wf2 = (const float*)d_in[16];
    const float* bf2 = (const float*)d_in[17];
    float* out = (float*)d_out;

    const int TB = 256;
    dim3 gridSD(STATS_BLKS + EDGE_BLKS, 3);
    dim3 gridE(EDGE_BLKS, 3);
    dim3 gridN((NN + TB - 1) / TB, 3);

    zeroK<<<(3 * NN + TB - 1) / TB, TB>>>();
    statsdegK<<<gridSD, TB>>>(x0, x1, x2, e0, e1, e2);
    coefK<<<1, 32>>>(nw, nb, nms, W1);
    z1K<<<gridN, TB>>>(x0, x1, x2);
    scat1K<<<gridE, TB>>>(e0, e1, e2);
    h1z2K<<<gridN, TB>>>(b1, W2);
    scat2K<<<gridE, TB>>>(e0, e1, e2);
    ff1K<<<NB, TB>>>(b2, wf1, bf1);
    ff2K<<<NB, TB>>>(wf2, bf2, mask, out);
}